// round 1
// baseline (speedup 1.0000x reference)
#include <cuda_runtime.h>
#include <cstdint>
#include <cstddef>

#define B_ 2
#define H_ 16
#define S_ 2048
#define D_ 128
#define TQ 16                 // query rows per CTA
#define KT 128                // keys per staged tile
#define NKT (S_/KT)           // 16
#define SC_PITCH 2052         // scores pitch (== 4 mod 32 -> conflict-free frag loads)
#define KV_PITCH_K 132        // K-tile pitch (== 4 mod 32)
#define KV_PITCH_V 136        // V-tile pitch (== 8 mod 32)
#define Q_PITCH 132
#define THREADS 256

#define SC_FLOATS (TQ*SC_PITCH)        // 32832
#define KV_FLOATS (KT*KV_PITCH_V)      // 17408 (max of the two pitches)
#define Q_FLOATS  (TQ*Q_PITCH)         // 2112
#define SMEM_BYTES ((SC_FLOATS + KV_FLOATS + Q_FLOATS)*4)   // 209408

__device__ __forceinline__ unsigned f2tf(float x){
    unsigned u; asm("cvt.rna.tf32.f32 %0, %1;" : "=r"(u) : "f"(x)); return u;
}

__device__ __forceinline__ void mma_tf32(float c[4],
    unsigned a0,unsigned a1,unsigned a2,unsigned a3, unsigned b0, unsigned b1){
    asm volatile("mma.sync.aligned.m16n8k8.row.col.f32.tf32.tf32.f32 "
        "{%0,%1,%2,%3}, {%4,%5,%6,%7}, {%8,%9}, {%0,%1,%2,%3};"
        : "+f"(c[0]),"+f"(c[1]),"+f"(c[2]),"+f"(c[3])
        : "r"(a0),"r"(a1),"r"(a2),"r"(a3),"r"(b0),"r"(b1));
}

__global__ __launch_bounds__(THREADS,1)
void attn_fused_kernel(
    const float* __restrict__ q, const float* __restrict__ k, const float* __restrict__ v,
    const int* __restrict__ mask, const float* __restrict__ bias,
    float* __restrict__ out, float* __restrict__ attn)
{
    extern __shared__ float smem[];
    float* sc = smem;                    // [TQ][SC_PITCH] raw scores -> exp -> attn(tf32)
    float* kv = smem + SC_FLOATS;        // staged K or V tile
    float* qs = kv + KV_FLOATS;          // staged Q tile (tf32 bit patterns)

    const int h  = blockIdx.x >> 1;
    const int b  = blockIdx.x & 1;
    const int qt = blockIdx.y;
    const int tid = threadIdx.x, warp = tid>>5, lane = tid&31;
    const int g = lane>>2, ctg = lane&3;
    const int q0 = qt*TQ;
    const size_t bh = (size_t)(b*H_ + h);
    const float* qp = q + (bh*S_ + q0)*(size_t)D_;
    const float* kp = k + bh*(size_t)S_*D_;
    const float* vp = v + bh*(size_t)S_*D_;

    // ---- stage Q tile (convert to tf32 once) ----
    for (int idx = tid; idx < TQ*(D_/4); idx += THREADS){
        int r = idx >> 5, c4 = (idx & 31)*4;
        float4 t = *(const float4*)(qp + r*D_ + c4);
        unsigned* dst = (unsigned*)(qs + r*Q_PITCH + c4);
        dst[0]=f2tf(t.x); dst[1]=f2tf(t.y); dst[2]=f2tf(t.z); dst[3]=f2tf(t.w);
    }

    const unsigned* qsu = (const unsigned*)qs;
    const unsigned* kvu = (const unsigned*)kv;

    // ---- QK^T: scores[16][2048] into SMEM ----
    for (int kt = 0; kt < NKT; ++kt){
        __syncthreads();
        for (int idx = tid; idx < KT*(D_/4); idx += THREADS){
            int r = idx >> 5, c4 = (idx & 31)*4;
            float4 t = *(const float4*)(kp + (size_t)(kt*KT + r)*D_ + c4);
            unsigned* dst = (unsigned*)(kv + r*KV_PITCH_K + c4);
            dst[0]=f2tf(t.x); dst[1]=f2tf(t.y); dst[2]=f2tf(t.z); dst[3]=f2tf(t.w);
        }
        __syncthreads();
        const int key0 = warp*16;
        float acc0[4] = {0,0,0,0}, acc1[4] = {0,0,0,0};
        #pragma unroll
        for (int dk = 0; dk < 16; ++dk){
            int dbase = dk*8;
            unsigned a0 = qsu[ g    *Q_PITCH + dbase + ctg];
            unsigned a1 = qsu[(g+8)*Q_PITCH + dbase + ctg];
            unsigned a2 = qsu[ g    *Q_PITCH + dbase + ctg + 4];
            unsigned a3 = qsu[(g+8)*Q_PITCH + dbase + ctg + 4];
            unsigned b0 = kvu[(key0+g  )*KV_PITCH_K + dbase + ctg];
            unsigned b1 = kvu[(key0+g  )*KV_PITCH_K + dbase + ctg + 4];
            mma_tf32(acc0, a0,a1,a2,a3, b0,b1);
            unsigned b2 = kvu[(key0+8+g)*KV_PITCH_K + dbase + ctg];
            unsigned b3 = kvu[(key0+8+g)*KV_PITCH_K + dbase + ctg + 4];
            mma_tf32(acc1, a0,a1,a2,a3, b2,b3);
        }
        int colbase = kt*KT + key0 + 2*ctg;
        *(float2*)(sc +  g   *SC_PITCH + colbase    ) = make_float2(acc0[0], acc0[1]);
        *(float2*)(sc + (g+8)*SC_PITCH + colbase    ) = make_float2(acc0[2], acc0[3]);
        *(float2*)(sc +  g   *SC_PITCH + colbase + 8) = make_float2(acc1[0], acc1[1]);
        *(float2*)(sc + (g+8)*SC_PITCH + colbase + 8) = make_float2(acc1[2], acc1[3]);
    }
    __syncthreads();

    // ---- scale + rel_bias + mask (coalesced gmem reads) ----
    const float scale = 0.0883883476483184406f;  // 1/sqrt(128)
    for (int r = 0; r < TQ; ++r){
        const float* bp = bias + ((size_t)h*S_ + q0 + r)*(size_t)S_;
        const int*   mp = mask + ((size_t)b*S_ + q0 + r)*(size_t)S_;
        float* row = sc + r*SC_PITCH;
        for (int c = tid; c < S_; c += THREADS){
            float s = row[c]*scale + bp[c];
            row[c] = (mp[c] == 0) ? -1e9f : s;
        }
    }
    __syncthreads();

    // ---- softmax per row (2 rows per warp); write attn to gmem, keep tf32 copy in SMEM ----
    float* attn_base = attn + (bh*S_ + q0)*(size_t)S_;
    #pragma unroll
    for (int rr = 0; rr < 2; ++rr){
        int r = warp*2 + rr;
        float* row = sc + r*SC_PITCH;
        float mx = -3.4e38f;
        for (int c = lane; c < S_; c += 32) mx = fmaxf(mx, row[c]);
        #pragma unroll
        for (int o = 16; o; o >>= 1) mx = fmaxf(mx, __shfl_xor_sync(0xffffffffu, mx, o));
        float sum = 0.f;
        for (int c = lane; c < S_; c += 32){ float e = __expf(row[c]-mx); row[c] = e; sum += e; }
        #pragma unroll
        for (int o = 16; o; o >>= 1) sum += __shfl_xor_sync(0xffffffffu, sum, o);
        float inv = 1.0f/sum;
        float* arow = attn_base + (size_t)r*S_;
        for (int c = lane; c < S_; c += 32){
            float a = row[c]*inv;
            arow[c] = a;                        // exact fp32 attn to output
            ((unsigned*)row)[c] = f2tf(a);      // tf32 copy for PV mma
        }
    }
    __syncthreads();

    // ---- PV: out[16][128] = attn @ V ----
    const unsigned* scu = (const unsigned*)sc;
    float o0[4] = {0,0,0,0}, o1[4] = {0,0,0,0};
    const int n0 = warp*16;
    for (int kt = 0; kt < NKT; ++kt){
        __syncthreads();
        for (int idx = tid; idx < KT*(D_/4); idx += THREADS){
            int r = idx >> 5, c4 = (idx & 31)*4;
            float4 t = *(const float4*)(vp + (size_t)(kt*KT + r)*D_ + c4);
            unsigned* dst = (unsigned*)(kv + r*KV_PITCH_V + c4);
            dst[0]=f2tf(t.x); dst[1]=f2tf(t.y); dst[2]=f2tf(t.z); dst[3]=f2tf(t.w);
        }
        __syncthreads();
        #pragma unroll
        for (int dk = 0; dk < 16; ++dk){
            int kb = kt*KT + dk*8;
            unsigned a0 = scu[ g    *SC_PITCH + kb + ctg];
            unsigned a1 = scu[(g+8)*SC_PITCH + kb + ctg];
            unsigned a2 = scu[ g    *SC_PITCH + kb + ctg + 4];
            unsigned a3 = scu[(g+8)*SC_PITCH + kb + ctg + 4];
            unsigned b0 = kvu[(dk*8+ctg  )*KV_PITCH_V + n0 + g];
            unsigned b1 = kvu[(dk*8+ctg+4)*KV_PITCH_V + n0 + g];
            mma_tf32(o0, a0,a1,a2,a3, b0,b1);
            unsigned b2 = kvu[(dk*8+ctg  )*KV_PITCH_V + n0 + 8 + g];
            unsigned b3 = kvu[(dk*8+ctg+4)*KV_PITCH_V + n0 + 8 + g];
            mma_tf32(o1, a0,a1,a2,a3, b2,b3);
        }
    }
    float* op = out + (bh*S_ + q0)*(size_t)D_;
    const int colb = n0 + 2*ctg;
    *(float2*)(op +  g   *D_ + colb    ) = make_float2(o0[0], o0[1]);
    *(float2*)(op + (g+8)*D_ + colb    ) = make_float2(o0[2], o0[3]);
    *(float2*)(op +  g   *D_ + colb + 8) = make_float2(o1[0], o1[1]);
    *(float2*)(op + (g+8)*D_ + colb + 8) = make_float2(o1[2], o1[3]);
}

extern "C" void kernel_launch(void* const* d_in, const int* in_sizes, int n_in,
                              void* d_out, int out_size)
{
    const float* q    = (const float*)d_in[0];
    const float* k    = (const float*)d_in[1];
    const float* v    = (const float*)d_in[2];
    const int*   mask = (const int*)  d_in[3];
    const float* bias = (const float*)d_in[4];
    float* out  = (float*)d_out;
    float* attn = out + (size_t)B_*H_*S_*D_;   // tuple output: (out, attn) concatenated

    cudaFuncSetAttribute(attn_fused_kernel,
                         cudaFuncAttributeMaxDynamicSharedMemorySize, SMEM_BYTES);
    dim3 grid(2*H_, S_/TQ);   // x = (h,b) interleaved for L2 sharing of mask/bias; y = q-tile
    attn_fused_kernel<<<grid, THREADS, SMEM_BYTES>>>(q, k, v, mask, bias, out, attn);
}

// round 2
// speedup vs baseline: 1.3038x; 1.3038x over previous
#include <cuda_runtime.h>
#include <cstdint>
#include <cstddef>

#define B_ 2
#define H_ 16
#define S_ 2048
#define D_ 128
#define THREADS 512
#define PITCH 132
#define TILE_FLOATS (128*PITCH)          // 16896
#define QS_OFF (3*TILE_FLOATS)           // 50688
#define RED_OFF (QS_OFF + 16*PITCH)      // 52800
#define SMEM_FLOATS (RED_OFF + 288)      // 53088
#define SMEM_BYTES (SMEM_FLOATS*4)       // 212352

__device__ __forceinline__ unsigned f2tf(float x){
    unsigned u; asm("cvt.rna.tf32.f32 %0, %1;" : "=r"(u) : "f"(x)); return u;
}
__device__ __forceinline__ void mma_tf32(float* c,
    unsigned a0,unsigned a1,unsigned a2,unsigned a3, unsigned b0, unsigned b1){
    asm volatile("mma.sync.aligned.m16n8k8.row.col.f32.tf32.tf32.f32 "
        "{%0,%1,%2,%3}, {%4,%5,%6,%7}, {%8,%9}, {%0,%1,%2,%3};"
        : "+f"(c[0]),"+f"(c[1]),"+f"(c[2]),"+f"(c[3])
        : "r"(a0),"r"(a1),"r"(a2),"r"(a3),"r"(b0),"r"(b1));
}
__device__ __forceinline__ void cpa16(float* dst, const float* src){
    unsigned d = (unsigned)__cvta_generic_to_shared(dst);
    asm volatile("cp.async.cg.shared.global [%0], [%1], 16;" :: "r"(d), "l"(src));
}
#define CP_COMMIT() asm volatile("cp.async.commit_group;")
#define CP_WAIT1()  asm volatile("cp.async.wait_group 1;")
#define CP_WAIT0()  asm volatile("cp.async.wait_group 0;")

__device__ __forceinline__ void load_tile(float* dst, const float* src, int tid){
    #pragma unroll
    for (int i=0;i<8;i++){
        int id = tid + i*THREADS;
        cpa16(dst + (id>>5)*PITCH + ((id&31)<<2), src + (id>>5)*D_ + ((id&31)<<2));
    }
}

__global__ __launch_bounds__(THREADS,1)
void attn_kernel(const float* __restrict__ q, const float* __restrict__ k,
                 const float* __restrict__ v, const int* __restrict__ mask,
                 const float* __restrict__ bias, float* __restrict__ out,
                 float* __restrict__ attn)
{
    extern __shared__ float smem[];
    float* qs  = smem + QS_OFF;
    float* red = smem + RED_OFF;

    const int tid = threadIdx.x, warp = tid>>5, lane = tid&31;
    const int g = lane>>2, ctg = lane&3;
    const int h = blockIdx.x>>1, b = blockIdx.x&1;
    const int q0 = blockIdx.y*16;
    const size_t bh = (size_t)(b*H_+h);
    const float* qp = q + (bh*S_+q0)*(size_t)D_;
    const float* kp = k + bh*(size_t)S_*D_;
    const float* vp = v + bh*(size_t)S_*D_;

    // ---- prologue: Q + K0 (group0), K1 (group1) ----
    { int r=tid>>5, c4=(tid&31)<<2; cpa16(qs + r*PITCH + c4, qp + r*D_ + c4); }
    load_tile(smem, kp, tid);
    CP_COMMIT();
    load_tile(smem + TILE_FLOATS, kp + 128*D_, tid);
    CP_COMMIT();
    CP_WAIT1(); __syncthreads();

    // convert+permute Q in place to tf32: within each 8-group, col c -> (c&3)*2 + (c>>2)
    if (tid < 256){
        int r = tid>>4, blk = tid&15;
        float* p = qs + r*PITCH + blk*8;
        float t[8];
        #pragma unroll
        for (int i=0;i<8;i++) t[i]=p[i];
        unsigned* up=(unsigned*)p;
        #pragma unroll
        for (int i=0;i<8;i++) up[(i&3)*2 + (i>>2)] = f2tf(t[i]);
    }

    float sacc[16][4];

    // ---- QK^T: 16 tiles, 3-stage cp.async pipeline ----
    #pragma unroll
    for (int kt=0; kt<16; ++kt){
        CP_WAIT1(); __syncthreads();
        const float* kb = smem + (kt%3)*TILE_FLOATS;
        float* acc = sacc[kt]; acc[0]=0.f; acc[1]=0.f; acc[2]=0.f; acc[3]=0.f;
        const unsigned* qrowL = (const unsigned*)(qs +  g   *PITCH) + 2*ctg;
        const unsigned* qrowH = (const unsigned*)(qs + (g+8)*PITCH) + 2*ctg;
        const float* krow = kb + (warp*8+g)*PITCH + ctg;
        #pragma unroll
        for (int dk=0; dk<16; ++dk){
            uint2 aL = *(const uint2*)(qrowL + dk*8);  // (a0, a2)
            uint2 aH = *(const uint2*)(qrowH + dk*8);  // (a1, a3)
            unsigned b0 = f2tf(krow[dk*8]);
            unsigned b1 = f2tf(krow[dk*8+4]);
            mma_tf32(acc, aL.x, aH.x, aL.y, aH.y, b0, b1);
        }
        if (kt < 14){
            load_tile(smem + ((kt+2)%3)*TILE_FLOATS, kp + (size_t)(kt+2)*128*D_, tid);
            CP_COMMIT();
        } else {
            // prefetch V0 (kt==14) / V1 (kt==15) — overlaps with softmax
            load_tile(smem + ((kt+2)%3)*TILE_FLOATS, vp + (size_t)(kt-14)*128*D_, tid);
            CP_COMMIT();
        }
    }

    // ---- scale + bias + mask + softmax on register scores ----
    const float scale = 0.08838834764831843f;
    const int colw = warp*8 + 2*ctg;
    const float* bLo = bias + ((size_t)h*S_ + q0+g)*S_ + colw;
    const float* bHi = bLo + 8*(size_t)S_;
    const int*   mLo = mask + ((size_t)b*S_ + q0+g)*S_ + colw;
    const int*   mHi = mLo + 8*(size_t)S_;
    float mxlo=-3.4e38f, mxhi=-3.4e38f;
    #pragma unroll
    for (int kt=0;kt<16;++kt){
        float2 b2l = *(const float2*)(bLo + kt*128);
        float2 b2h = *(const float2*)(bHi + kt*128);
        int2   m2l = *(const int2*)(mLo + kt*128);
        int2   m2h = *(const int2*)(mHi + kt*128);
        float* a = sacc[kt];
        a[0] = m2l.x ? fmaf(a[0],scale,b2l.x) : -1e9f;
        a[1] = m2l.y ? fmaf(a[1],scale,b2l.y) : -1e9f;
        a[2] = m2h.x ? fmaf(a[2],scale,b2h.x) : -1e9f;
        a[3] = m2h.y ? fmaf(a[3],scale,b2h.y) : -1e9f;
        mxlo = fmaxf(mxlo, fmaxf(a[0],a[1]));
        mxhi = fmaxf(mxhi, fmaxf(a[2],a[3]));
    }
    mxlo = fmaxf(mxlo, __shfl_xor_sync(~0u, mxlo, 1));
    mxlo = fmaxf(mxlo, __shfl_xor_sync(~0u, mxlo, 2));
    mxhi = fmaxf(mxhi, __shfl_xor_sync(~0u, mxhi, 1));
    mxhi = fmaxf(mxhi, __shfl_xor_sync(~0u, mxhi, 2));
    if (ctg==0){ red[warp*16+g]=mxlo; red[warp*16+8+g]=mxhi; }
    __syncthreads();
    if (tid<16){
        float m=-3.4e38f;
        #pragma unroll
        for (int wi=0; wi<16; ++wi) m = fmaxf(m, red[wi*16+tid]);
        red[256+tid]=m;
    }
    __syncthreads();
    mxlo = red[256+g]; mxhi = red[256+g+8];
    float smlo=0.f, smhi=0.f;
    #pragma unroll
    for (int kt=0;kt<16;++kt){
        float* a = sacc[kt];
        a[0]=__expf(a[0]-mxlo); a[1]=__expf(a[1]-mxlo);
        a[2]=__expf(a[2]-mxhi); a[3]=__expf(a[3]-mxhi);
        smlo += a[0]+a[1]; smhi += a[2]+a[3];
    }
    smlo += __shfl_xor_sync(~0u,smlo,1); smlo += __shfl_xor_sync(~0u,smlo,2);
    smhi += __shfl_xor_sync(~0u,smhi,1); smhi += __shfl_xor_sync(~0u,smhi,2);
    if (ctg==0){ red[warp*16+g]=smlo; red[warp*16+8+g]=smhi; }
    __syncthreads();
    if (tid<16){
        float s=0.f;
        #pragma unroll
        for (int wi=0;wi<16;++wi) s += red[wi*16+tid];
        red[272+tid] = 1.0f/s;
    }
    __syncthreads();
    {
        float invlo = red[272+g], invhi = red[272+g+8];
        float* aLo = attn + (bh*S_+q0+g)*(size_t)S_ + colw;
        float* aHi = aLo + 8*(size_t)S_;
        #pragma unroll
        for (int kt=0;kt<16;++kt){
            float* a=sacc[kt];
            a[0]*=invlo; a[1]*=invlo; a[2]*=invhi; a[3]*=invhi;
            *(float2*)(aLo + kt*128) = make_float2(a[0],a[1]);
            *(float2*)(aHi + kt*128) = make_float2(a[2],a[3]);
        }
    }

    // ---- PV: two n-halves (register pressure); attn A-frags via shfl transpose ----
    #pragma unroll
    for (int half=0; half<2; ++half){
        float oacc[8][4] = {};
        int bi = half ? 2 : 1;   // buffer of first tile of this pass
        #pragma unroll
        for (int jt=0; jt<16; ++jt){
            if (jt<15) { CP_WAIT1(); } else { CP_WAIT0(); }
            __syncthreads();
            const float* vb = smem + bi*TILE_FLOATS;
            float s0=sacc[jt][0], s1=sacc[jt][1], s2=sacc[jt][2], s3=sacc[jt][3];
            int lane1 = (g<<2) + (ctg>>1);
            float t00=__shfl_sync(~0u,s0,lane1),   t01=__shfl_sync(~0u,s1,lane1);
            float t10=__shfl_sync(~0u,s2,lane1),   t11=__shfl_sync(~0u,s3,lane1);
            float u00=__shfl_sync(~0u,s0,lane1+2), u01=__shfl_sync(~0u,s1,lane1+2);
            float u10=__shfl_sync(~0u,s2,lane1+2), u11=__shfl_sync(~0u,s3,lane1+2);
            bool sel = (ctg&1);
            unsigned a0=f2tf(sel?t01:t00), a1=f2tf(sel?t11:t10);
            unsigned a2=f2tf(sel?u01:u00), a3=f2tf(sel?u11:u10);
            const float* vrow = vb + (warp*8+ctg)*PITCH + half*64 + g;
            #pragma unroll
            for (int nb=0; nb<8; ++nb){
                unsigned b0 = f2tf(vrow[nb*8]);
                unsigned b1 = f2tf(vrow[4*PITCH + nb*8]);
                mma_tf32(oacc[nb], a0,a1,a2,a3, b0,b1);
            }
            if (jt < 14){
                int nbuf = bi - 1; if (nbuf < 0) nbuf = 2;   // (bi+2)%3
                load_tile(smem + nbuf*TILE_FLOATS, vp + (size_t)((jt+2)&15)*128*D_, tid);
                CP_COMMIT();
            }
            ++bi; if (bi==3) bi=0;
        }

        // ---- cross-warp out reduction (P overlay on buffer 0) ----
        __syncthreads();                     // all V reads done
        if (half==0){                        // prefetch pass-B V0 into buf2 (disjoint from P)
            load_tile(smem + 2*TILE_FLOATS, vp, tid); CP_COMMIT();
        }
        {
            float* P = smem + warp*1056 + lane*33;
            #pragma unroll
            for (int nb=0;nb<8;++nb){
                P[nb*4+0]=oacc[nb][0]; P[nb*4+1]=oacc[nb][1];
                P[nb*4+2]=oacc[nb][2]; P[nb*4+3]=oacc[nb][3];
            }
        }
        __syncthreads();
        {
            int ls = tid & 31, ib = tid >> 5;
            int gs = ls>>2, cs = ls&3;
            #pragma unroll
            for (int rep=0; rep<2; ++rep){
                int i = ib + rep*16;
                float s = 0.f;
                #pragma unroll
                for (int wi=0; wi<16; ++wi) s += smem[wi*1056 + ls*33 + i];
                int nb = i>>2, jj = i&3;
                int row = (jj<2) ? gs : gs+8;
                int col = half*64 + nb*8 + 2*cs + (jj&1);
                out[(bh*S_+q0+row)*(size_t)D_ + col] = s;
            }
        }
        if (half==0){
            __syncthreads();                 // P reads done before V1 overwrites buf0
            load_tile(smem, vp + 128*D_, tid); CP_COMMIT();   // pass-B V1 -> buf0
        }
    }
}

extern "C" void kernel_launch(void* const* d_in, const int* in_sizes, int n_in,
                              void* d_out, int out_size)
{
    const float* q    = (const float*)d_in[0];
    const float* k    = (const float*)d_in[1];
    const float* v    = (const float*)d_in[2];
    const int*   mask = (const int*)  d_in[3];
    const float* bias = (const float*)d_in[4];
    float* out  = (float*)d_out;
    float* attn = out + (size_t)B_*H_*S_*D_;   // tuple output: (out, attn)

    cudaFuncSetAttribute(attn_kernel,
                         cudaFuncAttributeMaxDynamicSharedMemorySize, SMEM_BYTES);
    dim3 grid(2*H_, S_/16);
    attn_kernel<<<grid, THREADS, SMEM_BYTES>>>(q, k, v, mask, bias, out, attn);
}